// round 12
// baseline (speedup 1.0000x reference)
#include <cuda_runtime.h>
#include <cuda_fp16.h>
#include <cstdint>

typedef __half f16;

#define M_ROWS  16384
#define DIM     1024
#define CB_IN   512
#define HEADS   8
#define CB_DIM  64
#define CB_SIZE 1024

// ---------------------------------------------------------------------------
// Device-global scratch
// ---------------------------------------------------------------------------
__device__ f16   g_x1[(size_t)M_ROWS * DIM];
__device__ f16   g_x2[(size_t)M_ROWS * DIM];
__device__ float g_hf[(size_t)M_ROWS * CB_IN];
__device__ f16   g_wi1[CB_IN * DIM];    // W_in^T splits
__device__ f16   g_wi2[CB_IN * DIM];
__device__ f16   g_e1[CB_SIZE * CB_DIM];
__device__ f16   g_e2[CB_SIZE * CB_DIM];
__device__ float g_esq[CB_SIZE];
__device__ f16   g_P[(size_t)HEADS * CB_SIZE * DIM];   // 16MB f16 code->out table
__device__ int   g_idx[(size_t)M_ROWS * HEADS];

// ---------------------------------------------------------------------------
// PTX helpers (sm_80-level, valid on compute_103)
// ---------------------------------------------------------------------------
__device__ __forceinline__ uint32_t smem_u32(const void* p) {
    uint32_t a;
    asm("{ .reg .u64 t; cvta.to.shared.u64 t, %1; cvt.u32.u64 %0, t; }" : "=r"(a) : "l"(p));
    return a;
}
#define LDM_X4(r0, r1, r2, r3, addr) \
    asm volatile("ldmatrix.sync.aligned.m8n8.x4.shared.b16 {%0,%1,%2,%3}, [%4];" \
                 : "=r"(r0), "=r"(r1), "=r"(r2), "=r"(r3) : "r"(addr))
#define MMA16816(c, a, b0_, b1_) \
    asm volatile("mma.sync.aligned.m16n8k16.row.col.f32.f16.f16.f32 " \
                 "{%0,%1,%2,%3}, {%4,%5,%6,%7}, {%8,%9}, {%0,%1,%2,%3};" \
                 : "+f"((c)[0]), "+f"((c)[1]), "+f"((c)[2]), "+f"((c)[3]) \
                 : "r"((a)[0]), "r"((a)[1]), "r"((a)[2]), "r"((a)[3]), \
                   "r"(b0_), "r"(b1_))
#define CP_ASYNC16(dst, src) \
    asm volatile("cp.async.cg.shared.global [%0], [%1], 16;" :: "r"(dst), "l"(src))
#define CP_COMMIT() asm volatile("cp.async.commit_group;" ::: "memory")
#define CP_WAIT1()  asm volatile("cp.async.wait_group 1;" ::: "memory")

// Tile: 128 rows x 128 bytes (64 f16), SW128-swizzled.
#define TILE_B 16384

// Warp tile m32 x n32; 16 warps cover 128x128.
struct LaneCtx {
    uint32_t aOff[2], aXor[2], aK;
    uint32_t bOff[2], bXor[2], bK;
};
__device__ __forceinline__ LaneCtx make_ctx(int lane, int warp_m, int warp_n) {
    LaneCtx c;
    int r = lane & 7, s = lane >> 3;
#pragma unroll
    for (int i = 0; i < 2; i++) {
        int row = warp_m * 32 + i * 16 + ((s & 1) << 3) + r;
        c.aOff[i] = row * 128;
        c.aXor[i] = (row & 7) << 4;
    }
    c.aK = (s >> 1) << 4;
#pragma unroll
    for (int p = 0; p < 2; p++) {
        int row = warp_n * 32 + p * 16 + ((s >> 1) << 3) + r;
        c.bOff[p] = row * 128;
        c.bXor[p] = (row & 7) << 4;
    }
    c.bK = (s & 1) << 4;
    return c;
}

__device__ __forceinline__ void mma_term(uint32_t aBase, uint32_t bBase,
                                         const LaneCtx& c, float (*acc)[4]) {
#pragma unroll
    for (int k16 = 0; k16 < 4; k16++) {
        uint32_t kb = k16 << 5;
        uint32_t a0[4], a1[4];
        LDM_X4(a0[0], a0[1], a0[2], a0[3], aBase + c.aOff[0] + ((kb + c.aK) ^ c.aXor[0]));
        LDM_X4(a1[0], a1[1], a1[2], a1[3], aBase + c.aOff[1] + ((kb + c.aK) ^ c.aXor[1]));
#pragma unroll
        for (int p = 0; p < 2; p++) {
            uint32_t b[4];
            LDM_X4(b[0], b[1], b[2], b[3], bBase + c.bOff[p] + ((kb + c.bK) ^ c.bXor[p]));
            MMA16816(acc[2 * p],         a0, b[0], b[1]);
            MMA16816(acc[2 * p + 1],     a0, b[2], b[3]);
            MMA16816(acc[4 + 2 * p],     a1, b[0], b[1]);
            MMA16816(acc[4 + 2 * p + 1], a1, b[2], b[3]);
        }
    }
}

// cp.async swizzled tile load, 512 threads: each thread 32B of one row
__device__ __forceinline__ void load_tile_cp(const f16* src, int rowStride,
                                             uint32_t tile, int tid) {
    int row = tid >> 2;
    int seg = (tid & 3) * 32;
    const char* s = (const char*)(src + (size_t)row * rowStride) + seg;
    uint32_t d = tile + row * 128;
    int xorv = (row & 7) << 4;
    CP_ASYNC16(d + (seg ^ xorv), s);
    CP_ASYNC16(d + ((seg + 16) ^ xorv), s + 16);
}

__device__ __forceinline__ void split2(float a, f16& h1, f16& h2) {
    h1 = __float2half_rn(a);
    h2 = __float2half_rn(a - __half2float(h1));
}

// ---------------------------------------------------------------------------
// Prep kernels (merged so fused_mma is the 4th launch -> ncu captures it)
// ---------------------------------------------------------------------------
// prepA: split x -> g_x1/g_x2
__global__ void prepA(const float* __restrict__ x) {
    int i = blockIdx.x * blockDim.x + threadIdx.x;
    if (i < M_ROWS * DIM) split2(x[i], g_x1[i], g_x2[i]);
}
// prepB: W_in^T splits (blocks 0..2047), embed splits (2048..2303), esq (2304..2431)
__global__ void prepB(const float* __restrict__ W_in, const float* __restrict__ embed) {
    int b = blockIdx.x;
    int tid = threadIdx.x;
    if (b < 2048) {                                  // wiT: 524288 elements
        int i = b * 256 + tid;
        int c = i / DIM, r = i - c * DIM;            // T[c*DIM + r] = W[r*CB_IN + c]
        split2(W_in[(size_t)r * CB_IN + c], g_wi1[i], g_wi2[i]);
    } else if (b < 2304) {                           // embed splits: 65536 elements
        int i = (b - 2048) * 256 + tid;
        split2(embed[i], g_e1[i], g_e2[i]);
    } else {                                         // esq: warp-per-code
        int w = (b - 2304) * 8 + (tid >> 5);
        int lane = tid & 31;
        const float2 v = *(const float2*)&embed[(size_t)w * CB_DIM + lane * 2];
        float s = fmaf(v.x, v.x, v.y * v.y);
#pragma unroll
        for (int off = 16; off > 0; off >>= 1)
            s += __shfl_xor_sync(0xFFFFFFFFu, s, off);
        if (lane == 0) g_esq[w] = s;
    }
}

// ---------------------------------------------------------------------------
// P table (f16): P[h][c][d] = sum_k embed[c][k] * W_out[h*64+k][d]
// ---------------------------------------------------------------------------
#define AS_LD 132
#define PTAB_SMEM (2 * 64 * AS_LD * 4)
__global__ __launch_bounds__(256)
void ptab_kernel(const float* __restrict__ embed, const float* __restrict__ W_out,
                 f16* __restrict__ P)
{
    extern __shared__ float smemf[];
    float* As = smemf;
    float* Bs = smemf + 64 * AS_LD;
    const int tid = threadIdx.x;
    const int tx = tid & 15, ty = tid >> 4;
    const int colb = blockIdx.x * 128, codeb = blockIdx.y * 128, head = blockIdx.z;

    {
        int r = tid >> 1, k0 = (tid & 1) * 32;
        const float* src = embed + (size_t)(codeb + r) * CB_DIM + k0;
#pragma unroll
        for (int j = 0; j < 8; j++) {
            float4 v = *(const float4*)(src + j * 4);
            As[(k0 + j * 4 + 0) * AS_LD + r] = v.x;
            As[(k0 + j * 4 + 1) * AS_LD + r] = v.y;
            As[(k0 + j * 4 + 2) * AS_LD + r] = v.z;
            As[(k0 + j * 4 + 3) * AS_LD + r] = v.w;
        }
    }
    {
        int k = tid >> 2, c4 = (tid & 3) * 32;
        const float* src = W_out + (size_t)(head * 64 + k) * DIM + colb + c4;
        float* dst = Bs + k * AS_LD + c4;
#pragma unroll
        for (int j = 0; j < 8; j++)
            *(float4*)(dst + j * 4) = *(const float4*)(src + j * 4);
    }
    __syncthreads();

    float acc[8][8];
#pragma unroll
    for (int i = 0; i < 8; i++)
#pragma unroll
        for (int j = 0; j < 8; j++) acc[i][j] = 0.f;
#pragma unroll
    for (int k = 0; k < 64; k++) {
        float ra[8], rb[8];
        const float* ak = As + k * AS_LD + ty * 8;
        const float* bk = Bs + k * AS_LD + tx * 8;
        *(float4*)&ra[0] = *(const float4*)(ak);
        *(float4*)&ra[4] = *(const float4*)(ak + 4);
        *(float4*)&rb[0] = *(const float4*)(bk);
        *(float4*)&rb[4] = *(const float4*)(bk + 4);
#pragma unroll
        for (int i = 0; i < 8; i++)
#pragma unroll
            for (int j = 0; j < 8; j++)
                acc[i][j] = fmaf(ra[i], rb[j], acc[i][j]);
    }
#pragma unroll
    for (int i = 0; i < 8; i++) {
        size_t o = ((size_t)head * CB_SIZE + codeb + ty * 8 + i) * DIM + colb + tx * 8;
        __half2* dst = (__half2*)&P[o];
#pragma unroll
        for (int j = 0; j < 4; j++)
            dst[j] = __floats2half2_rn(acc[i][2 * j], acc[i][2 * j + 1]);
    }
}

// ---------------------------------------------------------------------------
// FUSED: 3-stage cp.async pipeline, ONE __syncthreads per iteration.
// h = x @ W_in + b_in -> split h to smem -> score 2 heads vs codebook ->
// top-2 -> exact fp32 refine -> idx.  512 threads, warp grid 4x4.
// smem: 12 tiles (3 stages x 4) + esq + reduction.
// ---------------------------------------------------------------------------
#define VQ_RED (4 * 128)
#define FU_SMEM (12 * TILE_B + CB_SIZE * 4 + VQ_RED * 16)
__global__ __launch_bounds__(512)
void fused_mma(const f16* __restrict__ x1, const f16* __restrict__ x2,
               const f16* __restrict__ w1, const f16* __restrict__ w2,
               const float* __restrict__ b_in,
               const f16* __restrict__ e1, const f16* __restrict__ e2,
               const float* __restrict__ embed, const float* __restrict__ esq,
               float* __restrict__ hf,
               int* __restrict__ idx_out, float* __restrict__ ind_out)
{
    extern __shared__ char smem[];
    const int tid = threadIdx.x, lane = tid & 31, wid = tid >> 5;
    const int warp_m = wid & 3, warp_n = wid >> 2;
    const int m0 = blockIdx.y * 128, n0 = blockIdx.x * 128;

    uint32_t sb = smem_u32(smem);
    uint32_t stg[3][4];
#pragma unroll
    for (int s = 0; s < 3; s++)
#pragma unroll
        for (int t = 0; t < 4; t++) stg[s][t] = sb + (s * 4 + t) * TILE_B;

    float* esq_s  = (float*)(smem + 12 * TILE_B);
    float* r_best = (float*)(esq_s + CB_SIZE);
    float* r_sec  = r_best + VQ_RED;
    int*   r_bi   = (int*)(r_sec + VQ_RED);
    int*   r_si   = r_bi + VQ_RED;

    LaneCtx ctx = make_ctx(lane, warp_m, warp_n);
    float acc[8][4];
#pragma unroll
    for (int i = 0; i < 8; i++)
#pragma unroll
        for (int j = 0; j < 4; j++) acc[i][j] = 0.f;

    // ---------------- Phase 1: GEMM h = x @ W_in (3-stage, 1 sync/iter) ------
#pragma unroll
    for (int c = 0; c < 2; c++) {
        int kc = c * 64;
        load_tile_cp(x1 + (size_t)m0 * DIM + kc, DIM, stg[c][0], tid);
        load_tile_cp(x2 + (size_t)m0 * DIM + kc, DIM, stg[c][1], tid);
        load_tile_cp(w1 + (size_t)n0 * DIM + kc, DIM, stg[c][2], tid);
        load_tile_cp(w2 + (size_t)n0 * DIM + kc, DIM, stg[c][3], tid);
        CP_COMMIT();
    }
    for (int ci = 0; ci < 16; ci++) {
        CP_WAIT1();                 // chunk ci landed (for this thread)
        __syncthreads();            // -> landed for ALL; prior-iter reads done
        const int s = ci % 3;
        mma_term(stg[s][0], stg[s][2], ctx, acc);
        mma_term(stg[s][0], stg[s][3], ctx, acc);
        mma_term(stg[s][1], stg[s][2], ctx, acc);
        int nc = ci + 2;
        if (nc < 16) {
            int kc = nc * 64;
            const int sn = nc % 3;
            load_tile_cp(x1 + (size_t)m0 * DIM + kc, DIM, stg[sn][0], tid);
            load_tile_cp(x2 + (size_t)m0 * DIM + kc, DIM, stg[sn][1], tid);
            load_tile_cp(w1 + (size_t)n0 * DIM + kc, DIM, stg[sn][2], tid);
            load_tile_cp(w2 + (size_t)n0 * DIM + kc, DIM, stg[sn][3], tid);
        }
        CP_COMMIT();
    }
    __syncthreads();   // all phase-1 reads done before tiles are repurposed

    // ---------- Epilogue: bias + split into smem A-tiles (tiles 0-3) + hf ----
    const int g = lane >> 2, t4 = lane & 3;
#pragma unroll
    for (int i = 0; i < 2; i++) {
#pragma unroll
        for (int j = 0; j < 4; j++) {
            int col = warp_n * 32 + j * 8 + t4 * 2;
            int head = col >> 6, incol = col & 63;
            float b0 = __ldg(&b_in[n0 + col]), b1 = __ldg(&b_in[n0 + col + 1]);
            const float* a = acc[i * 4 + j];
#pragma unroll
            for (int z = 0; z < 2; z++) {
                int rloc = warp_m * 32 + i * 16 + z * 8 + g;
                float v0 = a[2 * z] + b0, v1 = a[2 * z + 1] + b1;
                f16 a1, a2, c1, c2;
                split2(v0, a1, a2);
                split2(v1, c1, c2);
                uint32_t byo = rloc * 128 + incol * 2;
                uint32_t swo = byo ^ ((rloc & 7) << 4);
                *(__half2*)(smem + (head * 2 + 0) * TILE_B + swo) = __half2(a1, c1);
                *(__half2*)(smem + (head * 2 + 1) * TILE_B + swo) = __half2(a2, c2);
                *(float2*)&hf[(size_t)(m0 + rloc) * CB_IN + n0 + col] = make_float2(v0, v1);
            }
        }
    }
    for (int i = tid; i < CB_SIZE; i += 512) esq_s[i] = esq[i];

    // B stages for phase 2: bstg[s] = tiles {4+2s, 5+2s}, s=0..2
    uint32_t bstg[3][2];
#pragma unroll
    for (int s = 0; s < 3; s++) {
        bstg[s][0] = sb + (4 + 2 * s) * TILE_B;
        bstg[s][1] = sb + (5 + 2 * s) * TILE_B;
    }
    // prologue: codebook chunks 0,1
#pragma unroll
    for (int c = 0; c < 2; c++) {
        load_tile_cp(e1 + (size_t)(c * 128) * CB_DIM, CB_DIM, bstg[c][0], tid);
        load_tile_cp(e2 + (size_t)(c * 128) * CB_DIM, CB_DIM, bstg[c][1], tid);
        CP_COMMIT();
    }

    // ---------------- Phase 2: score both heads (3-stage, 1 sync/iter) -------
    float best[2][4], sec[2][4];
    int   bi[2][4],  si[2][4];
#pragma unroll
    for (int h = 0; h < 2; h++)
#pragma unroll
        for (int s = 0; s < 4; s++) {
            best[h][s] = -3.4e38f; sec[h][s] = -3.4e38f; bi[h][s] = 0; si[h][s] = 1;
        }

    for (int ci = 0; ci < 8; ci++) {
        CP_WAIT1();
        __syncthreads();     // codebook chunk ci visible; also A-tile stores (iter 0)
        const int s = ci % 3;
        const int c0 = ci * 128;
#pragma unroll
        for (int h = 0; h < 2; h++) {
            float sacc[8][4];
#pragma unroll
            for (int i = 0; i < 8; i++)
#pragma unroll
                for (int j = 0; j < 4; j++) sacc[i][j] = 0.f;
            uint32_t a1t = sb + (h * 2 + 0) * TILE_B;
            uint32_t a2t = sb + (h * 2 + 1) * TILE_B;
            mma_term(a1t, bstg[s][0], ctx, sacc);
            mma_term(a1t, bstg[s][1], ctx, sacc);
            mma_term(a2t, bstg[s][0], ctx, sacc);
#pragma unroll
            for (int i = 0; i < 2; i++)
#pragma unroll
                for (int z = 0; z < 2; z++) {
                    int slot = i * 2 + z;
#pragma unroll
                    for (int j = 0; j < 4; j++)
#pragma unroll
                        for (int w = 0; w < 2; w++) {
                            int cix = c0 + warp_n * 32 + j * 8 + t4 * 2 + w;
                            float sc = 2.f * sacc[i * 4 + j][z * 2 + w] - esq_s[cix];
                            if (sc > best[h][slot]) {
                                sec[h][slot] = best[h][slot]; si[h][slot] = bi[h][slot];
                                best[h][slot] = sc; bi[h][slot] = cix;
                            } else if (sc > sec[h][slot]) {
                                sec[h][slot] = sc; si[h][slot] = cix;
                            }
                        }
                }
        }
        int nc = ci + 2;
        if (nc < 8) {
            const int sn = nc % 3;
            load_tile_cp(e1 + (size_t)(nc * 128) * CB_DIM, CB_DIM, bstg[sn][0], tid);
            load_tile_cp(e2 + (size_t)(nc * 128) * CB_DIM, CB_DIM, bstg[sn][1], tid);
        }
        CP_COMMIT();
    }
    __syncthreads();

    // ---------------- Merge + exact refine, per head ----------------
#pragma unroll
    for (int h = 0; h < 2; h++) {
        float hb[4], hs[4];
        int   hbi[4], hsi[4];
#pragma unroll
        for (int s = 0; s < 4; s++) {
            hb[s] = best[h][s]; hs[s] = sec[h][s]; hbi[s] = bi[h][s]; hsi[s] = si[h][s];
        }
#pragma unroll
        for (int slot = 0; slot < 4; slot++) {
#pragma unroll
            for (int off = 1; off <= 2; off <<= 1) {
                float ob = __shfl_xor_sync(0xFFFFFFFFu, hb[slot],  off);
                int   oi = __shfl_xor_sync(0xFFFFFFFFu, hbi[slot], off);
                float os = __shfl_xor_sync(0xFFFFFFFFu, hs[slot],  off);
                int   oj = __shfl_xor_sync(0xFFFFFFFFu, hsi[slot], off);
                if (ob > hb[slot] || (ob == hb[slot] && oi < hbi[slot])) {
                    float cb = hb[slot]; int ci2 = hbi[slot];
                    if (os > cb || (os == cb && oj < ci2)) { cb = os; ci2 = oj; }
                    hb[slot] = ob; hbi[slot] = oi; hs[slot] = cb; hsi[slot] = ci2;
                } else {
                    if (ob > hs[slot] || (ob == hs[slot] && oi < hsi[slot])) {
                        hs[slot] = ob; hsi[slot] = oi;
                    }
                }
            }
        }
        if (t4 == 0) {
#pragma unroll
            for (int slot = 0; slot < 4; slot++) {
                int row = warp_m * 32 + (slot >> 1) * 16 + (slot & 1) * 8 + g;
                int o = warp_n * 128 + row;
                r_best[o] = hb[slot]; r_bi[o] = hbi[slot];
                r_sec[o]  = hs[slot]; r_si[o] = hsi[slot];
            }
        }
        __syncthreads();

        if (tid < 128) {
            float bb = r_best[tid], ss = r_sec[tid];
            int   bbi = r_bi[tid],  ssi = r_si[tid];
#pragma unroll
            for (int gq = 1; gq < 4; gq++) {
                int o = gq * 128 + tid;
                float ob = r_best[o], os = r_sec[o];
                int   oi = r_bi[o],   oj = r_si[o];
                if (ob > bb || (ob == bb && oi < bbi)) {
                    float cb = bb; int ci2 = bbi;
                    if (os > cb || (os == cb && oj < ci2)) { cb = os; ci2 = oj; }
                    bb = ob; bbi = oi; ss = cb; ssi = ci2;
                } else {
                    if (ob > ss || (ob == ss && oi < ssi)) { ss = ob; ssi = oi; }
                }
            }
            int cA = bbi, cB = ssi;
            const int headg = (n0 >> 6) + h;
            const float* hrow = hf + (size_t)(m0 + tid) * CB_IN + headg * CB_DIM;
            const float* eA = embed + (size_t)cA * CB_DIM;
            const float* eB = embed + (size_t)cB * CB_DIM;
            float dA = 0.f, dB = 0.f;
#pragma unroll
            for (int k = 0; k < CB_DIM; k += 4) {
                float4 hv = *(const float4*)(hrow + k);
                float4 av = *(const float4*)(eA + k);
                float4 bv = *(const float4*)(eB + k);
                dA = fmaf(hv.x, av.x, dA); dA = fmaf(hv.y, av.y, dA);
                dA = fmaf(hv.z, av.z, dA); dA = fmaf(hv.w, av.w, dA);
                dB = fmaf(hv.x, bv.x, dB); dB = fmaf(hv.y, bv.y, dB);
                dB = fmaf(hv.z, bv.z, dB); dB = fmaf(hv.w, bv.w, dB);
            }
            float sA = 2.f * dA - esq_s[cA];
            float sB = 2.f * dB - esq_s[cB];
            int idx = (sB > sA || (sB == sA && cB < cA)) ? cB : cA;

            idx_out[(size_t)(m0 + tid) * HEADS + headg] = idx;
            if (ind_out)
                ind_out[(size_t)(m0 + tid) * HEADS + headg] = (float)idx;
        }
        __syncthreads();
    }
}

// ---------------------------------------------------------------------------
// out[row][:] = b_out + sum_h P_f16[h][idx[row][h]][:]   (one row per CTA)
// ---------------------------------------------------------------------------
__global__ __launch_bounds__(256)
void out_gather(const int* __restrict__ idx, const f16* __restrict__ P,
                const float* __restrict__ b_out, float* __restrict__ out)
{
    __shared__ int s_idx[HEADS];
    const int row = blockIdx.x;
    const int tid = threadIdx.x;
    if (tid < HEADS) s_idx[tid] = idx[(size_t)row * HEADS + tid];
    __syncthreads();

    int col = tid * 4;
    float4 acc = *(const float4*)&b_out[col];
#pragma unroll
    for (int h = 0; h < HEADS; h++) {
        const __half2* p = (const __half2*)&P[((size_t)h * CB_SIZE + s_idx[h]) * DIM + col];
        float2 p0 = __half22float2(p[0]);
        float2 p1 = __half22float2(p[1]);
        acc.x += p0.x; acc.y += p0.y; acc.z += p1.x; acc.w += p1.y;
    }
    *(float4*)&out[(size_t)row * DIM + col] = acc;
}

// ---------------------------------------------------------------------------
extern "C" void kernel_launch(void* const* d_in, const int* in_sizes, int n_in,
                              void* d_out, int out_size) {
    const float* x     = (const float*)d_in[0];
    const float* W_in  = (const float*)d_in[1];
    const float* b_in  = (const float*)d_in[2];
    const float* W_out = (const float*)d_in[3];
    const float* b_out = (const float*)d_in[4];
    const float* embed = (const float*)d_in[5];

    float* out = (float*)d_out;
    float* ind_out = nullptr;
    if ((long long)out_size >= (long long)M_ROWS * DIM + (long long)M_ROWS * HEADS)
        ind_out = out + (size_t)M_ROWS * DIM;

    f16 *x1, *x2, *wi1, *wi2, *e1, *e2, *P;
    float *hf, *esq;
    int* idxp;
    cudaGetSymbolAddress((void**)&x1, g_x1);   cudaGetSymbolAddress((void**)&x2, g_x2);
    cudaGetSymbolAddress((void**)&hf, g_hf);
    cudaGetSymbolAddress((void**)&wi1, g_wi1); cudaGetSymbolAddress((void**)&wi2, g_wi2);
    cudaGetSymbolAddress((void**)&e1, g_e1);   cudaGetSymbolAddress((void**)&e2, g_e2);
    cudaGetSymbolAddress((void**)&esq, g_esq); cudaGetSymbolAddress((void**)&P, g_P);
    cudaGetSymbolAddress((void**)&idxp, g_idx);

    static bool attr_set = false;
    if (!attr_set) {
        cudaFuncSetAttribute(fused_mma,   cudaFuncAttributeMaxDynamicSharedMemorySize, FU_SMEM);
        cudaFuncSetAttribute(ptab_kernel, cudaFuncAttributeMaxDynamicSharedMemorySize, PTAB_SMEM);
        attr_set = true;
    }

    // 1) x splits  2) W_in^T splits + embed splits + esq  3) P table
    prepA<<<(M_ROWS * DIM + 255) / 256, 256>>>(x);
    prepB<<<2432, 256>>>(W_in, embed);
    ptab_kernel<<<dim3(DIM / 128, CB_SIZE / 128, HEADS), 256, PTAB_SMEM>>>(embed, W_out, P);
    // 4) fused GEMM1 + VQ  (4th launch -> ncu capture target)
    fused_mma<<<dim3(CB_IN / 128, M_ROWS / 128), 512, FU_SMEM>>>(
        x1, x2, wi1, wi2, b_in, e1, e2, embed, esq, hf, idxp, ind_out);
    // 5) out = b_out + sum_h P[h][idx]
    out_gather<<<M_ROWS, 256>>>(idxp, P, b_out, out);
}

// round 15
// speedup vs baseline: 1.3699x; 1.3699x over previous
#include <cuda_runtime.h>
#include <cuda_fp16.h>
#include <cstdint>

typedef __half f16;

#define M_ROWS  16384
#define DIM     1024
#define CB_IN   512
#define HEADS   8
#define CB_DIM  64
#define CB_SIZE 1024

// ---------------------------------------------------------------------------
// Device-global scratch
// ---------------------------------------------------------------------------
__device__ f16   g_x1[(size_t)M_ROWS * DIM];
__device__ f16   g_x2[(size_t)M_ROWS * DIM];
__device__ float g_hf[(size_t)M_ROWS * CB_IN];
__device__ f16   g_wi1[CB_IN * DIM];    // W_in^T splits
__device__ f16   g_wi2[CB_IN * DIM];
__device__ f16   g_e1[CB_SIZE * CB_DIM];
__device__ f16   g_e2[CB_SIZE * CB_DIM];
__device__ float g_esq[CB_SIZE];
__device__ f16   g_P[(size_t)HEADS * CB_SIZE * DIM];   // 16MB f16 code->out table
__device__ int   g_idx[(size_t)M_ROWS * HEADS];

// ---------------------------------------------------------------------------
// PTX helpers (sm_80-level, valid on compute_103)
// ---------------------------------------------------------------------------
__device__ __forceinline__ uint32_t smem_u32(const void* p) {
    uint32_t a;
    asm("{ .reg .u64 t; cvta.to.shared.u64 t, %1; cvt.u32.u64 %0, t; }" : "=r"(a) : "l"(p));
    return a;
}
#define LDM_X4(r0, r1, r2, r3, addr) \
    asm volatile("ldmatrix.sync.aligned.m8n8.x4.shared.b16 {%0,%1,%2,%3}, [%4];" \
                 : "=r"(r0), "=r"(r1), "=r"(r2), "=r"(r3) : "r"(addr))
#define MMA16816(c, a, b0_, b1_) \
    asm volatile("mma.sync.aligned.m16n8k16.row.col.f32.f16.f16.f32 " \
                 "{%0,%1,%2,%3}, {%4,%5,%6,%7}, {%8,%9}, {%0,%1,%2,%3};" \
                 : "+f"((c)[0]), "+f"((c)[1]), "+f"((c)[2]), "+f"((c)[3]) \
                 : "r"((a)[0]), "r"((a)[1]), "r"((a)[2]), "r"((a)[3]), \
                   "r"(b0_), "r"(b1_))
#define CP_ASYNC16(dst, src) \
    asm volatile("cp.async.cg.shared.global [%0], [%1], 16;" :: "r"(dst), "l"(src))
#define CP_COMMIT() asm volatile("cp.async.commit_group;" ::: "memory")
#define CP_WAIT1()  asm volatile("cp.async.wait_group 1;" ::: "memory")

// Tile: 128 rows x 128 bytes (64 f16), SW128-swizzled.
#define TILE_B 16384

// Warp tile m32 x n32; 16 warps cover 128x128.
struct LaneCtx {
    uint32_t aOff[2], aXor[2], aK;
    uint32_t bOff[2], bXor[2], bK;
};
__device__ __forceinline__ LaneCtx make_ctx(int lane, int warp_m, int warp_n) {
    LaneCtx c;
    int r = lane & 7, s = lane >> 3;
#pragma unroll
    for (int i = 0; i < 2; i++) {
        int row = warp_m * 32 + i * 16 + ((s & 1) << 3) + r;
        c.aOff[i] = row * 128;
        c.aXor[i] = (row & 7) << 4;
    }
    c.aK = (s >> 1) << 4;
#pragma unroll
    for (int p = 0; p < 2; p++) {
        int row = warp_n * 32 + p * 16 + ((s >> 1) << 3) + r;
        c.bOff[p] = row * 128;
        c.bXor[p] = (row & 7) << 4;
    }
    c.bK = (s & 1) << 4;
    return c;
}

// Fused 3-term (a1b1 + a1b2 + a2b1) over K=64 with shared fragment loads.
// acc[8][4]: acc[i*4.. ] layout: (m-atom i, b-atom p, n8 half) as before.
__device__ __forceinline__ void mma_term3(uint32_t a1B, uint32_t a2B,
                                          uint32_t b1B, uint32_t b2B,
                                          const LaneCtx& c, float (*acc)[4]) {
#pragma unroll
    for (int k16 = 0; k16 < 4; k16++) {
        uint32_t kb = k16 << 5;
        uint32_t a10[4], a11[4], a20[4], a21[4];
        uint32_t ao0 = ((kb + c.aK) ^ c.aXor[0]) + c.aOff[0];
        uint32_t ao1 = ((kb + c.aK) ^ c.aXor[1]) + c.aOff[1];
        LDM_X4(a10[0], a10[1], a10[2], a10[3], a1B + ao0);
        LDM_X4(a11[0], a11[1], a11[2], a11[3], a1B + ao1);
        LDM_X4(a20[0], a20[1], a20[2], a20[3], a2B + ao0);
        LDM_X4(a21[0], a21[1], a21[2], a21[3], a2B + ao1);
#pragma unroll
        for (int p = 0; p < 2; p++) {
            uint32_t bo = ((kb + c.bK) ^ c.bXor[p]) + c.bOff[p];
            uint32_t b1[4], b2[4];
            LDM_X4(b1[0], b1[1], b1[2], b1[3], b1B + bo);
            LDM_X4(b2[0], b2[1], b2[2], b2[3], b2B + bo);
            // a1*b1
            MMA16816(acc[2 * p],         a10, b1[0], b1[1]);
            MMA16816(acc[2 * p + 1],     a10, b1[2], b1[3]);
            MMA16816(acc[4 + 2 * p],     a11, b1[0], b1[1]);
            MMA16816(acc[4 + 2 * p + 1], a11, b1[2], b1[3]);
            // a1*b2
            MMA16816(acc[2 * p],         a10, b2[0], b2[1]);
            MMA16816(acc[2 * p + 1],     a10, b2[2], b2[3]);
            MMA16816(acc[4 + 2 * p],     a11, b2[0], b2[1]);
            MMA16816(acc[4 + 2 * p + 1], a11, b2[2], b2[3]);
            // a2*b1
            MMA16816(acc[2 * p],         a20, b1[0], b1[1]);
            MMA16816(acc[2 * p + 1],     a20, b1[2], b1[3]);
            MMA16816(acc[4 + 2 * p],     a21, b1[0], b1[1]);
            MMA16816(acc[4 + 2 * p + 1], a21, b1[2], b1[3]);
        }
    }
}

// cp.async swizzled tile load, 512 threads: each thread 32B of one row
__device__ __forceinline__ void load_tile_cp(const f16* src, int rowStride,
                                             uint32_t tile, int tid) {
    int row = tid >> 2;
    int seg = (tid & 3) * 32;
    const char* s = (const char*)(src + (size_t)row * rowStride) + seg;
    uint32_t d = tile + row * 128;
    int xorv = (row & 7) << 4;
    CP_ASYNC16(d + (seg ^ xorv), s);
    CP_ASYNC16(d + ((seg + 16) ^ xorv), s + 16);
}

__device__ __forceinline__ void split2(float a, f16& h1, f16& h2) {
    h1 = __float2half_rn(a);
    h2 = __float2half_rn(a - __half2float(h1));
}

// ---------------------------------------------------------------------------
// Prep kernels (merged so fused_mma is the 4th launch -> ncu captures it)
// ---------------------------------------------------------------------------
__global__ void prepA(const float* __restrict__ x) {
    int i = blockIdx.x * blockDim.x + threadIdx.x;
    if (i < M_ROWS * DIM) split2(x[i], g_x1[i], g_x2[i]);
}
__global__ void prepB(const float* __restrict__ W_in, const float* __restrict__ embed) {
    int b = blockIdx.x;
    int tid = threadIdx.x;
    if (b < 2048) {                                  // W_in^T splits
        int i = b * 256 + tid;
        int c = i / DIM, r = i - c * DIM;
        split2(W_in[(size_t)r * CB_IN + c], g_wi1[i], g_wi2[i]);
    } else if (b < 2304) {                           // embed splits
        int i = (b - 2048) * 256 + tid;
        split2(embed[i], g_e1[i], g_e2[i]);
    } else {                                         // esq: warp-per-code
        int w = (b - 2304) * 8 + (tid >> 5);
        int lane = tid & 31;
        const float2 v = *(const float2*)&embed[(size_t)w * CB_DIM + lane * 2];
        float s = fmaf(v.x, v.x, v.y * v.y);
#pragma unroll
        for (int off = 16; off > 0; off >>= 1)
            s += __shfl_xor_sync(0xFFFFFFFFu, s, off);
        if (lane == 0) g_esq[w] = s;
    }
}

// ---------------------------------------------------------------------------
// P table (f16): P[h][c][d] = sum_k embed[c][k] * W_out[h*64+k][d]
// ---------------------------------------------------------------------------
#define AS_LD 132
#define PTAB_SMEM (2 * 64 * AS_LD * 4)
__global__ __launch_bounds__(256)
void ptab_kernel(const float* __restrict__ embed, const float* __restrict__ W_out,
                 f16* __restrict__ P)
{
    extern __shared__ float smemf[];
    float* As = smemf;
    float* Bs = smemf + 64 * AS_LD;
    const int tid = threadIdx.x;
    const int tx = tid & 15, ty = tid >> 4;
    const int colb = blockIdx.x * 128, codeb = blockIdx.y * 128, head = blockIdx.z;

    {
        int r = tid >> 1, k0 = (tid & 1) * 32;
        const float* src = embed + (size_t)(codeb + r) * CB_DIM + k0;
#pragma unroll
        for (int j = 0; j < 8; j++) {
            float4 v = *(const float4*)(src + j * 4);
            As[(k0 + j * 4 + 0) * AS_LD + r] = v.x;
            As[(k0 + j * 4 + 1) * AS_LD + r] = v.y;
            As[(k0 + j * 4 + 2) * AS_LD + r] = v.z;
            As[(k0 + j * 4 + 3) * AS_LD + r] = v.w;
        }
    }
    {
        int k = tid >> 2, c4 = (tid & 3) * 32;
        const float* src = W_out + (size_t)(head * 64 + k) * DIM + colb + c4;
        float* dst = Bs + k * AS_LD + c4;
#pragma unroll
        for (int j = 0; j < 8; j++)
            *(float4*)(dst + j * 4) = *(const float4*)(src + j * 4);
    }
    __syncthreads();

    float acc[8][8];
#pragma unroll
    for (int i = 0; i < 8; i++)
#pragma unroll
        for (int j = 0; j < 8; j++) acc[i][j] = 0.f;
#pragma unroll
    for (int k = 0; k < 64; k++) {
        float ra[8], rb[8];
        const float* ak = As + k * AS_LD + ty * 8;
        const float* bk = Bs + k * AS_LD + tx * 8;
        *(float4*)&ra[0] = *(const float4*)(ak);
        *(float4*)&ra[4] = *(const float4*)(ak + 4);
        *(float4*)&rb[0] = *(const float4*)(bk);
        *(float4*)&rb[4] = *(const float4*)(bk + 4);
#pragma unroll
        for (int i = 0; i < 8; i++)
#pragma unroll
            for (int j = 0; j < 8; j++)
                acc[i][j] = fmaf(ra[i], rb[j], acc[i][j]);
    }
#pragma unroll
    for (int i = 0; i < 8; i++) {
        size_t o = ((size_t)head * CB_SIZE + codeb + ty * 8 + i) * DIM + colb + tx * 8;
        __half2* dst = (__half2*)&P[o];
#pragma unroll
        for (int j = 0; j < 4; j++)
            dst[j] = __floats2half2_rn(acc[i][2 * j], acc[i][2 * j + 1]);
    }
}

// ---------------------------------------------------------------------------
// FUSED (R11-proven 2-stage skeleton + fragment-shared mma_term3):
// h = x @ W_in + b_in -> split h to smem -> score 2 heads vs codebook ->
// top-2 -> exact fp32 refine -> idx.  512 threads, warp grid 4x4.
// ---------------------------------------------------------------------------
#define VQ_RED (4 * 128)
#define FU_SMEM (8 * TILE_B + CB_SIZE * 4 + VQ_RED * 16)
__global__ __launch_bounds__(512)
void fused_mma(const f16* __restrict__ x1, const f16* __restrict__ x2,
               const f16* __restrict__ w1, const f16* __restrict__ w2,
               const float* __restrict__ b_in,
               const f16* __restrict__ e1, const f16* __restrict__ e2,
               const float* __restrict__ embed, const float* __restrict__ esq,
               float* __restrict__ hf,
               int* __restrict__ idx_out, float* __restrict__ ind_out)
{
    extern __shared__ char smem[];
    const int tid = threadIdx.x, lane = tid & 31, wid = tid >> 5;
    const int warp_m = wid & 3, warp_n = wid >> 2;
    const int m0 = blockIdx.y * 128, n0 = blockIdx.x * 128;

    uint32_t sb = smem_u32(smem);
    uint32_t stg[2][4];
#pragma unroll
    for (int s = 0; s < 2; s++)
#pragma unroll
        for (int t = 0; t < 4; t++) stg[s][t] = sb + (s * 4 + t) * TILE_B;

    float* esq_s  = (float*)(smem + 8 * TILE_B);
    float* r_best = (float*)(esq_s + CB_SIZE);
    float* r_sec  = r_best + VQ_RED;
    int*   r_bi   = (int*)(r_sec + VQ_RED);
    int*   r_si   = r_bi + VQ_RED;

    LaneCtx ctx = make_ctx(lane, warp_m, warp_n);
    float acc[8][4];
#pragma unroll
    for (int i = 0; i < 8; i++)
#pragma unroll
        for (int j = 0; j < 4; j++) acc[i][j] = 0.f;

    // ---------------- Phase 1: GEMM h = x @ W_in ----------------
#pragma unroll
    for (int c = 0; c < 2; c++) {
        int kc = c * 64;
        load_tile_cp(x1 + (size_t)m0 * DIM + kc, DIM, stg[c][0], tid);
        load_tile_cp(x2 + (size_t)m0 * DIM + kc, DIM, stg[c][1], tid);
        load_tile_cp(w1 + (size_t)n0 * DIM + kc, DIM, stg[c][2], tid);
        load_tile_cp(w2 + (size_t)n0 * DIM + kc, DIM, stg[c][3], tid);
        CP_COMMIT();
    }
    for (int ci = 0; ci < 16; ci++) {
        CP_WAIT1();
        __syncthreads();
        int s = ci & 1;
        mma_term3(stg[s][0], stg[s][1], stg[s][2], stg[s][3], ctx, acc);
        __syncthreads();
        int nc = ci + 2;
        if (nc < 16) {
            int kc = nc * 64;
            load_tile_cp(x1 + (size_t)m0 * DIM + kc, DIM, stg[s][0], tid);
            load_tile_cp(x2 + (size_t)m0 * DIM + kc, DIM, stg[s][1], tid);
            load_tile_cp(w1 + (size_t)n0 * DIM + kc, DIM, stg[s][2], tid);
            load_tile_cp(w2 + (size_t)n0 * DIM + kc, DIM, stg[s][3], tid);
        }
        CP_COMMIT();
    }
    __syncthreads();   // all phase-1 reads done before tiles repurposed

    // ---------- Epilogue: bias + split into smem A-tiles (tiles 0-3) + hf ----
    const int g = lane >> 2, t4 = lane & 3;
#pragma unroll
    for (int i = 0; i < 2; i++) {
#pragma unroll
        for (int j = 0; j < 4; j++) {
            int col = warp_n * 32 + j * 8 + t4 * 2;
            int head = col >> 6, incol = col & 63;
            float b0 = __ldg(&b_in[n0 + col]), b1 = __ldg(&b_in[n0 + col + 1]);
            const float* a = acc[i * 4 + j];
#pragma unroll
            for (int z = 0; z < 2; z++) {
                int rloc = warp_m * 32 + i * 16 + z * 8 + g;
                float v0 = a[2 * z] + b0, v1 = a[2 * z + 1] + b1;
                f16 a1, a2, c1, c2;
                split2(v0, a1, a2);
                split2(v1, c1, c2);
                uint32_t byo = rloc * 128 + incol * 2;
                uint32_t swo = byo ^ ((rloc & 7) << 4);
                *(__half2*)(smem + (head * 2 + 0) * TILE_B + swo) = __half2(a1, c1);
                *(__half2*)(smem + (head * 2 + 1) * TILE_B + swo) = __half2(a2, c2);
                *(float2*)&hf[(size_t)(m0 + rloc) * CB_IN + n0 + col] = make_float2(v0, v1);
            }
        }
    }
    for (int i = tid; i < CB_SIZE; i += 512) esq_s[i] = esq[i];

    // B prologue: codebook chunks 0,1 into tiles 4..7
#pragma unroll
    for (int c = 0; c < 2; c++) {
        load_tile_cp(e1 + (size_t)(c * 128) * CB_DIM, CB_DIM, stg[1][c * 2 + 0], tid);
        load_tile_cp(e2 + (size_t)(c * 128) * CB_DIM, CB_DIM, stg[1][c * 2 + 1], tid);
        CP_COMMIT();
    }

    // ---------------- Phase 2: score both heads vs codebook ----------------
    float best[2][4], sec[2][4];
    int   bi[2][4],  si[2][4];
#pragma unroll
    for (int h = 0; h < 2; h++)
#pragma unroll
        for (int s = 0; s < 4; s++) {
            best[h][s] = -3.4e38f; sec[h][s] = -3.4e38f; bi[h][s] = 0; si[h][s] = 1;
        }

    for (int ci = 0; ci < 8; ci++) {
        CP_WAIT1();
        __syncthreads();          // also orders A-tile stores before first use
        int s = ci & 1;
        int c0 = ci * 128;
#pragma unroll
        for (int h = 0; h < 2; h++) {
            float sacc[8][4];
#pragma unroll
            for (int i = 0; i < 8; i++)
#pragma unroll
                for (int j = 0; j < 4; j++) sacc[i][j] = 0.f;
            mma_term3(sb + (h * 2 + 0) * TILE_B, sb + (h * 2 + 1) * TILE_B,
                      stg[1][s * 2 + 0], stg[1][s * 2 + 1], ctx, sacc);
#pragma unroll
            for (int i = 0; i < 2; i++)
#pragma unroll
                for (int z = 0; z < 2; z++) {
                    int slot = i * 2 + z;
#pragma unroll
                    for (int j = 0; j < 4; j++)
#pragma unroll
                        for (int w = 0; w < 2; w++) {
                            int cix = c0 + warp_n * 32 + j * 8 + t4 * 2 + w;
                            float sc = 2.f * sacc[i * 4 + j][z * 2 + w] - esq_s[cix];
                            if (sc > best[h][slot]) {
                                sec[h][slot] = best[h][slot]; si[h][slot] = bi[h][slot];
                                best[h][slot] = sc; bi[h][slot] = cix;
                            } else if (sc > sec[h][slot]) {
                                sec[h][slot] = sc; si[h][slot] = cix;
                            }
                        }
                }
        }
        __syncthreads();
        int nc = ci + 2;
        if (nc < 8) {
            load_tile_cp(e1 + (size_t)(nc * 128) * CB_DIM, CB_DIM, stg[1][s * 2 + 0], tid);
            load_tile_cp(e2 + (size_t)(nc * 128) * CB_DIM, CB_DIM, stg[1][s * 2 + 1], tid);
        }
        CP_COMMIT();
    }

    // ---------------- Merge + exact refine, per head ----------------
#pragma unroll
    for (int h = 0; h < 2; h++) {
        float hb[4], hs[4];
        int   hbi[4], hsi[4];
#pragma unroll
        for (int s = 0; s < 4; s++) {
            hb[s] = best[h][s]; hs[s] = sec[h][s]; hbi[s] = bi[h][s]; hsi[s] = si[h][s];
        }
#pragma unroll
        for (int slot = 0; slot < 4; slot++) {
#pragma unroll
            for (int off = 1; off <= 2; off <<= 1) {
                float ob = __shfl_xor_sync(0xFFFFFFFFu, hb[slot],  off);
                int   oi = __shfl_xor_sync(0xFFFFFFFFu, hbi[slot], off);
                float os = __shfl_xor_sync(0xFFFFFFFFu, hs[slot],  off);
                int   oj = __shfl_xor_sync(0xFFFFFFFFu, hsi[slot], off);
                if (ob > hb[slot] || (ob == hb[slot] && oi < hbi[slot])) {
                    float cb = hb[slot]; int ci2 = hbi[slot];
                    if (os > cb || (os == cb && oj < ci2)) { cb = os; ci2 = oj; }
                    hb[slot] = ob; hbi[slot] = oi; hs[slot] = cb; hsi[slot] = ci2;
                } else {
                    if (ob > hs[slot] || (ob == hs[slot] && oi < hsi[slot])) {
                        hs[slot] = ob; hsi[slot] = oi;
                    }
                }
            }
        }
        if (t4 == 0) {
#pragma unroll
            for (int slot = 0; slot < 4; slot++) {
                int row = warp_m * 32 + (slot >> 1) * 16 + (slot & 1) * 8 + g;
                int o = warp_n * 128 + row;
                r_best[o] = hb[slot]; r_bi[o] = hbi[slot];
                r_sec[o]  = hs[slot]; r_si[o] = hsi[slot];
            }
        }
        __syncthreads();

        if (tid < 128) {
            float bb = r_best[tid], ss = r_sec[tid];
            int   bbi = r_bi[tid],  ssi = r_si[tid];
#pragma unroll
            for (int gq = 1; gq < 4; gq++) {
                int o = gq * 128 + tid;
                float ob = r_best[o], os = r_sec[o];
                int   oi = r_bi[o],   oj = r_si[o];
                if (ob > bb || (ob == bb && oi < bbi)) {
                    float cb = bb; int ci2 = bbi;
                    if (os > cb || (os == cb && oj < ci2)) { cb = os; ci2 = oj; }
                    bb = ob; bbi = oi; ss = cb; ssi = ci2;
                } else {
                    if (ob > ss || (ob == ss && oi < ssi)) { ss = ob; ssi = oi; }
                }
            }
            int cA = bbi, cB = ssi;
            const int headg = (n0 >> 6) + h;
            const float* hrow = hf + (size_t)(m0 + tid) * CB_IN + headg * CB_DIM;
            const float* eA = embed + (size_t)cA * CB_DIM;
            const float* eB = embed + (size_t)cB * CB_DIM;
            float dA = 0.f, dB = 0.f;
#pragma unroll
            for (int k = 0; k < CB_DIM; k += 4) {
                float4 hv = *(const float4*)(hrow + k);
                float4 av = *(const float4*)(eA + k);
                float4 bv = *(const float4*)(eB + k);
                dA = fmaf(hv.x, av.x, dA); dA = fmaf(hv.y, av.y, dA);
                dA = fmaf(hv.z, av.z, dA); dA = fmaf(hv.w, av.w, dA);
                dB = fmaf(hv.x, bv.x, dB); dB = fmaf(hv.y, bv.y, dB);
                dB = fmaf(hv.z, bv.z, dB); dB = fmaf(hv.w, bv.w, dB);
            }
            float sA = 2.f * dA - esq_s[cA];
            float sB = 2.f * dB - esq_s[cB];
            int idx = (sB > sA || (sB == sA && cB < cA)) ? cB : cA;

            idx_out[(size_t)(m0 + tid) * HEADS + headg] = idx;
            if (ind_out)
                ind_out[(size_t)(m0 + tid) * HEADS + headg] = (float)idx;
        }
        __syncthreads();
    }
}

// ---------------------------------------------------------------------------
// out[row][:] = b_out + sum_h P_f16[h][idx[row][h]][:]   (one row per CTA)
// ---------------------------------------------------------------------------
__global__ __launch_bounds__(256)
void out_gather(const int* __restrict__ idx, const f16* __restrict__ P,
                const float* __restrict__ b_out, float* __restrict__ out)
{
    __shared__ int s_idx[HEADS];
    const int row = blockIdx.x;
    const int tid = threadIdx.x;
    if (tid < HEADS) s_idx[tid] = idx[(size_t)row * HEADS + tid];
    __syncthreads();

    int col = tid * 4;
    float4 acc = *(const float4*)&b_out[col];
#pragma unroll
    for (int h = 0; h < HEADS; h++) {
        const __half2* p = (const __half2*)&P[((size_t)h * CB_SIZE + s_idx[h]) * DIM + col];
        float2 p0 = __half22float2(p[0]);
        float2 p1 = __half22float2(p[1]);
        acc.x += p0.x; acc.y += p0.y; acc.z += p1.x; acc.w += p1.y;
    }
    *(float4*)&out[(size_t)row * DIM + col] = acc;
}

// ---------------------------------------------------------------------------
extern "C" void kernel_launch(void* const* d_in, const int* in_sizes, int n_in,
                              void* d_out, int out_size) {
    const float* x     = (const float*)d_in[0];
    const float* W_in  = (const float*)d_in[1];
    const float* b_in  = (const float*)d_in[2];
    const float* W_out = (const float*)d_in[3];
    const float* b_out = (const float*)d_in[4];
    const float* embed = (const float*)d_in[5];

    float* out = (float*)d_out;
    float* ind_out = nullptr;
    if ((long long)out_size >= (long long)M_ROWS * DIM + (long long)M_ROWS * HEADS)
        ind_out = out + (size_t)M_ROWS * DIM;

    f16 *x1, *x2, *wi1, *wi2, *e1, *e2, *P;
    float *hf, *esq;
    int* idxp;
    cudaGetSymbolAddress((void**)&x1, g_x1);   cudaGetSymbolAddress((void**)&x2, g_x2);
    cudaGetSymbolAddress((void**)&hf, g_hf);
    cudaGetSymbolAddress((void**)&wi1, g_wi1); cudaGetSymbolAddress((void**)&wi2, g_wi2);
    cudaGetSymbolAddress((void**)&e1, g_e1);   cudaGetSymbolAddress((void**)&e2, g_e2);
    cudaGetSymbolAddress((void**)&esq, g_esq); cudaGetSymbolAddress((void**)&P, g_P);
    cudaGetSymbolAddress((void**)&idxp, g_idx);

    static bool attr_set = false;
    if (!attr_set) {
        cudaFuncSetAttribute(fused_mma,   cudaFuncAttributeMaxDynamicSharedMemorySize, FU_SMEM);
        cudaFuncSetAttribute(ptab_kernel, cudaFuncAttributeMaxDynamicSharedMemorySize, PTAB_SMEM);
        attr_set = true;
    }

    // 1) x splits  2) W_in^T splits + embed splits + esq  3) P table
    prepA<<<(M_ROWS * DIM + 255) / 256, 256>>>(x);
    prepB<<<2432, 256>>>(W_in, embed);
    ptab_kernel<<<dim3(DIM / 128, CB_SIZE / 128, HEADS), 256, PTAB_SMEM>>>(embed, W_out, P);
    // 4) fused GEMM1 + VQ  (4th launch -> ncu capture target)
    fused_mma<<<dim3(CB_IN / 128, M_ROWS / 128), 512, FU_SMEM>>>(
        x1, x2, wi1, wi2, b_in, e1, e2, embed, esq, hf, idxp, ind_out);
    // 5) out = b_out + sum_h P[h][idx]
    out_gather<<<M_ROWS, 256>>>(idxp, P, b_out, out);
}